// round 14
// baseline (speedup 1.0000x reference)
#include <cuda_runtime.h>

#define BB 256
#define SS 1024
#define NT 128
#define CPRE 5.5f

__device__ float g_logZ[BB];
__device__ float g_score[BB];

static __device__ __forceinline__ unsigned long long pk2(float x, float y) {
    unsigned long long r;
    asm("mov.b64 %0, {%1, %2};" : "=l"(r) : "f"(x), "f"(y));
    return r;
}
static __device__ __forceinline__ void upk2(float& x, float& y, unsigned long long v) {
    asm("mov.b64 {%0, %1}, %2;" : "=f"(x), "=f"(y) : "l"(v));
}
static __device__ __forceinline__ void ffma2(unsigned long long& d, unsigned long long a, unsigned long long b) {
    asm("fma.rn.f32x2 %0, %1, %2, %0;" : "+l"(d) : "l"(a), "l"(b));
}

// Padded alpha index: i-group g (32 rows) starts at 36g floats -> the four
// groups' LDS.128 hit disjoint bank quads; same-group lanes broadcast.
#define AIDX(i) ((i) + (((i) >> 5) << 2))

// Forward recurrence. 256 CTAs x 512 threads, 1 batch/CTA, 2 CTAs/SM
// (8 warps/SMSP total; co-resident CTA hides barrier/chain stalls).
// Thread (ig=tid&3, jg=tid>>2) owns exp(T) rows [32ig,32ig+32) x col jg in
// 16 packed regs (32 floats) -> no spill under the 64-reg occ-2 cap.
__global__ __launch_bounds__(512, 2) void crf_forward(
    const float* __restrict__ em, const float* __restrict__ tr,
    const float* __restrict__ mask)
{
    __shared__ __align__(16) float sA[2][144];
    __shared__ __align__(16) float sW[16];

    const int tid  = threadIdx.x;
    const int ig   = tid & 3;
    const int jg   = tid >> 2;
    const int i0   = ig << 5;
    const int lane = tid & 31;
    const int wid  = tid >> 5;
    const int b    = blockIdx.x;

    // exp(T) quarter-column -> 16 packed regs (pair p = rows i0+2p, i0+2p+1)
    unsigned long long E[16];
#pragma unroll
    for (int p = 0; p < 16; ++p) {
        float r0 = tr[(i0 + 2 * p) * NT + jg];
        float r1 = tr[(i0 + 2 * p + 1) * NT + jg];
        E[p] = pk2(__expf(r0), __expf(r1));
    }

    const float* eb = em + (size_t)b * SS * NT;
    const float* mb = mask + b * SS;

    float lg = 0.0f;
    // t = 0 init: alpha = exp(emissions[:,0,:])
    if (ig == 0) sA[0][AIDX(jg)] = __expf(eb[jg]);

    // preload emissions/mask for steps 1..2
    float emB[2], mkB[2];
#pragma unroll
    for (int u = 0; u < 2; ++u) {
        emB[u] = eb[(size_t)(1 + u) * NT + jg];
        mkB[u] = mb[1 + u];
    }
    __syncthreads();

    for (int tb = 1; tb < SS; tb += 2) {
        // prefetch steps tb+2, tb+3 (2-step distance; sequential stream)
        float emN[2], mkN[2];
#pragma unroll
        for (int u = 0; u < 2; ++u) {
            int tp = tb + 2 + u; if (tp > SS - 1) tp = SS - 1;
            emN[u] = eb[(size_t)tp * NT + jg];
            mkN[u] = mb[tp];
        }

#pragma unroll
        for (int u = 0; u < 2; ++u) {
            const int t = tb + u;
            if (t < SS) {
                const int cur = t & 1, prv = cur ^ 1;
                const bool renorm = ((t & 31) == 0);        // t = 32, 64, ...
                const bool dow    = (((t + 1) & 31) == 0);  // publish at 31, 63, ...

                float rinv = 1.0f, Mv = 1.0f;
                if (renorm) {
                    float m = -1.0f;
#pragma unroll
                    for (int q = 0; q < 4; ++q) {
                        float4 w = *(const float4*)&sW[4 * q];
                        m = fmaxf(m, fmaxf(fmaxf(w.x, w.y), fmaxf(w.z, w.w)));
                    }
                    Mv = m;
                    asm("rcp.approx.f32 %0, %1;" : "=f"(rinv) : "f"(Mv));
                }

                // quarter-dot over 32 rows: 2 chains of 8 FFMA2
                unsigned long long a0 = 0ull, a1 = 0ull;
#pragma unroll
                for (int c = 0; c < 8; ++c) {
                    ulonglong2 v = *(const ulonglong2*)&sA[prv][AIDX(i0) + 4 * c];
                    ffma2(a0, v.x, E[2 * c]);
                    ffma2(a1, v.y, E[2 * c + 1]);
                }
                float lo, hi, l2, h2;
                upk2(lo, hi, a0); upk2(l2, h2, a1);
                float d = (lo + hi) + (l2 + h2);
                // combine the four i-quarters (lanes differ in bits 0-1)
                d += __shfl_xor_sync(0xffffffffu, d, 1);
                d += __shfl_xor_sync(0xffffffffu, d, 2);

                float nv;
                if (mkB[u] != 0.0f) {
                    float s = __expf(emB[u] - CPRE);
                    lg += CPRE;
                    if (renorm) { s *= rinv; lg += __logf(Mv); }
                    nv = d * s;
                    if (ig == 0) sA[cur][AIDX(jg)] = nv;
                } else {
                    nv = sA[prv][AIDX(jg)];
                    if (ig == 0) sA[cur][AIDX(jg)] = nv;
                }
                if (dow) {
                    // nv equal across bits 0-1 of lane; max over the 8 jg-quads
                    float wm = nv;
#pragma unroll
                    for (int s2 = 16; s2 >= 4; s2 >>= 1)
                        wm = fmaxf(wm, __shfl_xor_sync(0xffffffffu, wm, s2));
                    if (lane == 0) sW[wid] = wm;
                }
            }
            __syncthreads();
        }

#pragma unroll
        for (int u = 0; u < 2; ++u) { emB[u] = emN[u]; mkB[u] = mkN[u]; }
    }

    // logZ = log(sum alpha) + accumulated log-scales (t=1023 wrote sA[1])
    if (wid == 0) {
        float s = 0.0f;
#pragma unroll
        for (int k = 0; k < 4; ++k) s += sA[1][AIDX(lane + 32 * k)];
#pragma unroll
        for (int d2 = 16; d2; d2 >>= 1) s += __shfl_xor_sync(0xffffffffu, s, d2);
        if (lane == 0) g_logZ[b] = __logf(s) + lg;
    }
}

// Gold-path score: 256 threads x 4 contiguous timesteps.
__global__ __launch_bounds__(256) void crf_score(
    const float* __restrict__ em, const float* __restrict__ tr,
    const int* __restrict__ tags, const float* __restrict__ mask)
{
    const int b = blockIdx.x;
    const int tid = threadIdx.x;
    const int t0 = tid * 4;
    const int* tg = tags + b * SS;
    const float* mk = mask + b * SS;
    const float* ebase = em + (size_t)b * SS * NT;

    int4   tg4 = *(const int4*)(tg + t0);
    float4 mk4 = *(const float4*)(mk + t0);

    float e0 = ebase[(size_t)(t0 + 0) * NT + tg4.x];
    float e1 = ebase[(size_t)(t0 + 1) * NT + tg4.y];
    float e2 = ebase[(size_t)(t0 + 2) * NT + tg4.z];
    float e3 = ebase[(size_t)(t0 + 3) * NT + tg4.w];

    float r0 = 0.0f;
    if (t0 > 0) { int tp = tg[t0 - 1]; r0 = tr[tp * NT + tg4.x]; }
    float r1 = tr[tg4.x * NT + tg4.y];
    float r2 = tr[tg4.y * NT + tg4.z];
    float r3 = tr[tg4.z * NT + tg4.w];

    float acc = (e0 + r0) * mk4.x + (e1 + r1) * mk4.y
              + (e2 + r2) * mk4.z + (e3 + r3) * mk4.w;

#pragma unroll
    for (int d = 16; d; d >>= 1) acc += __shfl_xor_sync(0xffffffffu, acc, d);
    __shared__ float red[8];
    if ((tid & 31) == 0) red[tid >> 5] = acc;
    __syncthreads();
    if (tid == 0) {
        float s = 0.0f;
#pragma unroll
        for (int w = 0; w < 8; ++w) s += red[w];
        g_score[b] = s;
    }
}

__global__ __launch_bounds__(BB) void crf_final(float* __restrict__ out) {
    const int tid = threadIdx.x;
    float v = g_logZ[tid] - g_score[tid];
#pragma unroll
    for (int d = 16; d; d >>= 1) v += __shfl_xor_sync(0xffffffffu, v, d);
    __shared__ float red[8];
    if ((tid & 31) == 0) red[tid >> 5] = v;
    __syncthreads();
    if (tid == 0) {
        float s = 0.0f;
#pragma unroll
        for (int w = 0; w < 8; ++w) s += red[w];
        out[0] = s * (1.0f / BB);
    }
}

extern "C" void kernel_launch(void* const* d_in, const int* in_sizes, int n_in,
                              void* d_out, int out_size) {
    (void)in_sizes; (void)n_in; (void)out_size;
    const float* em   = (const float*)d_in[0];
    const float* tr   = (const float*)d_in[1];
    const int*   tags = (const int*)d_in[2];
    const float* mask = (const float*)d_in[3];
    crf_score<<<BB, 256>>>(em, tr, tags, mask);
    crf_forward<<<BB, 512>>>(em, tr, mask);
    crf_final<<<1, BB>>>((float*)d_out);
}